// round 16
// baseline (speedup 1.0000x reference)
#include <cuda_runtime.h>
#include <cstdint>

// Inputs (metadata order):
//   0 origins [N,3] f32   1 directions [N,3] f32   2 center [3] f32
//   3 radius  [1]  f32    4 W1 [3,128] f32         5 b1 [128] f32
//   6 W2 [128,3] f32      7 b2 [3] f32
// Output: color [N,3] f32
//
// Tensor-core MLP: per warp, 32 rays = two m16 tiles.
//   GEMM1: [16 rays x 8(K: x,y,z,1,0,0,0,0)] @ W1'[8 x 128]  (b1 folded as row 3)
//   relu -> h staged in smem (per-warp, stride 132 floats, conflict-free)
//   GEMM2: [16 x 128] @ W2'[128 x 8(3 used)]  via 16 k-steps
// All tf32 inputs rounded with cvt.rna (expected aggregate rel_err ~2e-4 < 1e-3).

#define MAX_ITERS 64
#define TPB 128
#define WPB 4            // warps per block
#define HSTRIDE 132      // h row stride in floats (128 + 4 pad -> bank-shift 4)

static __device__ __forceinline__ unsigned cvt_tf32(float x) {
    unsigned u;
    asm("cvt.rna.tf32.f32 %0, %1;" : "=r"(u) : "f"(x));
    return u;
}
static __device__ __forceinline__ float fsqrt_fast(float x) {
    float y;
    asm("sqrt.approx.f32 %0, %1;" : "=f"(y) : "f"(x));
    return y;
}
// D += A@B, m16n8k8 tf32, A row-major frag, B col-major frag.
static __device__ __forceinline__ void mma_tf32(
    float& d0, float& d1, float& d2, float& d3,
    unsigned a0, unsigned a1, unsigned a2, unsigned a3,
    unsigned b0, unsigned b1)
{
    asm("mma.sync.aligned.m16n8k8.row.col.f32.tf32.tf32.f32 "
        "{%0,%1,%2,%3}, {%4,%5,%6,%7}, {%8,%9}, {%0,%1,%2,%3};"
        : "+f"(d0), "+f"(d1), "+f"(d2), "+f"(d3)
        : "r"(a0), "r"(a1), "r"(a2), "r"(a3), "r"(b0), "r"(b1));
}
static __device__ __forceinline__ float sigmoidf_fast(float z) {
    return __fdividef(1.0f, 1.0f + __expf(-z));
}

__global__ __launch_bounds__(TPB, 4)
void sphere_trace_mlp_kernel(
    const float* __restrict__ origins,
    const float* __restrict__ dirs,
    const float* __restrict__ center,
    const float* __restrict__ radius,
    const float* __restrict__ W1,   // [3,128] row-major
    const float* __restrict__ b1,   // [128]
    const float* __restrict__ W2,   // [128,3] row-major
    const float* __restrict__ b2,   // [3]
    float* __restrict__ out,        // [N,3]
    int n)
{
    __shared__ unsigned Ps[WPB][32 * 4];          // tf32 bits of (x,y,z,1) per ray
    __shared__ unsigned Hs[WPB][16 * HSTRIDE];    // h tile (tf32 bits), per warp

    const int tid  = threadIdx.x;
    const int lane = tid & 31;
    const int wid  = tid >> 5;
    const int gr   = lane >> 2;    // fragment row group
    const int gc   = lane & 3;     // fragment col group
    const int rbase = (blockIdx.x * WPB + wid) * 32;   // warp's first ray

    // ---- Resident weight fragments (loaded once, tf32-rounded) ----
    // GEMM1 B [k8 x n8]: b0 = W1'[k=gc? no: k=lane&3][unit=8nb+lane>>2]; rows 4-7 = 0.
    unsigned w1b[16];
    unsigned w2b0[16], w2b1[16];
    {
        const int col  = lane >> 2;   // n index within 8
        const int krow = lane & 3;    // k index within 4
        #pragma unroll
        for (int nb = 0; nb < 16; ++nb) {
            const int unit = 8 * nb + col;
            const float v = (krow < 3) ? W1[krow * 128 + unit] : b1[unit];
            w1b[nb] = cvt_tf32(v);
        }
        #pragma unroll
        for (int ks = 0; ks < 16; ++ks) {
            const int k0 = 8 * ks + krow;
            w2b0[ks] = (col < 3) ? cvt_tf32(W2[k0 * 3 + col])       : 0u;
            w2b1[ks] = (col < 3) ? cvt_tf32(W2[(k0 + 4) * 3 + col]) : 0u;
        }
    }

    // ---- Per-lane ray trace / classification (1 ray per lane) ----
    const int ray = rbase + lane;
    const int i   = (ray < n) ? ray : (n - 1);
    const float cx = center[0], cy = center[1], cz = center[2];
    const float r  = radius[0];
    const float r2 = r * r;

    const float ox = origins[3 * i], oy = origins[3 * i + 1], oz = origins[3 * i + 2];
    const float dx = dirs[3 * i],    dy = dirs[3 * i + 1],    dz = dirs[3 * i + 2];

    const float ux = ox - cx, uy = oy - cy, uz = oz - cz;
    const float c0q  = fmaf(ux, ux, fmaf(uy, uy, uz * uz));
    const float hb   = fmaf(ux, dx, fmaf(uy, dy, uz * dz));
    const float disc = fmaf(hb, hb, r2 - c0q);
    const bool  toward = (hb < 0.0f);
    bool hit = toward && (disc > 0.04f * r2);
    const bool in_band = toward && !hit && (disc > -2e-4f);
    float t = hit ? (-hb - fsqrt_fast(disc)) : 0.0f;
    float px = fmaf(t, dx, ox), py = fmaf(t, dy, oy), pz = fmaf(t, dz, oz);

    if (__any_sync(0xffffffffu, in_band)) {
        // Rare (~1e-4 of warps): exact 64-iter reference recurrence, all lanes.
        const float b = 2.0f * hb;
        float tt = 0.0f, s = 0.0f;
        #pragma unroll 1
        for (int it = 0; it < MAX_ITERS; ++it) {
            s = sqrtf(fmaf(tt, tt + b, c0q)) - r;
            tt += s;
        }
        hit = (s < 1e-4f);
        px = fmaf(tt, dx, ox); py = fmaf(tt, dy, oy); pz = fmaf(tt, dz, oz);
    }

    const unsigned hitmask = __ballot_sync(0xffffffffu, hit && (ray < n));

    // Stage p (tf32 bits) for fragment assembly.
    {
        unsigned* P = &Ps[wid][lane * 4];
        P[0] = cvt_tf32(px);
        P[1] = cvt_tf32(py);
        P[2] = cvt_tf32(pz);
        P[3] = cvt_tf32(1.0f);
    }
    __syncwarp();

    const float bb0 = b2[0], bb1 = b2[1], bb2 = b2[2];
    const unsigned* __restrict__ Pw = Ps[wid];
    unsigned* __restrict__ H = Hs[wid];

    #pragma unroll
    for (int tsel = 0; tsel < 2; ++tsel) {
        // A1 fragment: a0 = P[row gr][k gc], a1 = P[row gr+8][k gc]; cols 4-7 zero.
        const unsigned a0 = Pw[(tsel * 16 + gr) * 4 + gc];
        const unsigned a1 = Pw[(tsel * 16 + gr + 8) * 4 + gc];

        // GEMM1: 16 chunks of 8 units; relu; store h to smem in row-major tf32.
        #pragma unroll
        for (int nb = 0; nb < 16; ++nb) {
            float d0 = 0.f, d1 = 0.f, d2 = 0.f, d3 = 0.f;
            mma_tf32(d0, d1, d2, d3, a0, a1, 0u, 0u, w1b[nb], 0u);
            d0 = fmaxf(d0, 0.f); d1 = fmaxf(d1, 0.f);
            d2 = fmaxf(d2, 0.f); d3 = fmaxf(d3, 0.f);
            // C frag: (c0,c1) = rows gr, cols 8nb+2gc,+1; (c2,c3) = rows gr+8.
            const int cb = 8 * nb + 2 * gc;
            *(uint2*)&H[gr * HSTRIDE + cb] =
                make_uint2(cvt_tf32(d0), cvt_tf32(d1));
            *(uint2*)&H[(gr + 8) * HSTRIDE + cb] =
                make_uint2(cvt_tf32(d2), cvt_tf32(d3));
        }
        __syncwarp();

        // GEMM2: 16 k-steps; A2 frag read straight from H in A-layout.
        float c0 = 0.f, c1 = 0.f, c2 = 0.f, c3 = 0.f;
        #pragma unroll
        for (int ks = 0; ks < 16; ++ks) {
            const int kb = 8 * ks;
            const unsigned ua0 = H[gr * HSTRIDE + kb + gc];
            const unsigned ua1 = H[(gr + 8) * HSTRIDE + kb + gc];
            const unsigned ua2 = H[gr * HSTRIDE + kb + gc + 4];
            const unsigned ua3 = H[(gr + 8) * HSTRIDE + kb + gc + 4];
            mma_tf32(c0, c1, c2, c3, ua0, ua1, ua2, ua3, w2b0[ks], w2b1[ks]);
        }
        __syncwarp();   // H reused by next tsel

        // Epilogue: C frag cols 0-2 are the color channels.
        const int lr0 = tsel * 16 + gr;
        const int lr1 = lr0 + 8;
        const int r0 = rbase + lr0, r1 = rbase + lr1;
        const bool m0 = (hitmask >> lr0) & 1u;
        const bool m1 = (hitmask >> lr1) & 1u;
        if (gc == 0) {          // cols 0,1 -> ch0, ch1
            if (r0 < n) {
                out[3 * r0]     = m0 ? sigmoidf_fast(c0 + bb0) : 0.0f;
                out[3 * r0 + 1] = m0 ? sigmoidf_fast(c1 + bb1) : 0.0f;
            }
            if (r1 < n) {
                out[3 * r1]     = m1 ? sigmoidf_fast(c2 + bb0) : 0.0f;
                out[3 * r1 + 1] = m1 ? sigmoidf_fast(c3 + bb1) : 0.0f;
            }
        } else if (gc == 1) {   // col 2 -> ch2
            if (r0 < n) out[3 * r0 + 2] = m0 ? sigmoidf_fast(c0 + bb2) : 0.0f;
            if (r1 < n) out[3 * r1 + 2] = m1 ? sigmoidf_fast(c2 + bb2) : 0.0f;
        }
    }
}

extern "C" void kernel_launch(void* const* d_in, const int* in_sizes, int n_in,
                              void* d_out, int out_size) {
    const float* origins = (const float*)d_in[0];
    const float* dirs    = (const float*)d_in[1];
    const float* center  = (const float*)d_in[2];
    const float* radius  = (const float*)d_in[3];
    const float* W1      = (const float*)d_in[4];
    const float* b1      = (const float*)d_in[5];
    const float* W2      = (const float*)d_in[6];
    const float* b2      = (const float*)d_in[7];
    float* out = (float*)d_out;

    const int n = in_sizes[0] / 3;
    const int rays_per_block = TPB / 32 * 32 * WPB / WPB * 32;  // 4 warps * 32 rays
    (void)rays_per_block;
    const int blocks = (n + (WPB * 32) - 1) / (WPB * 32);
    sphere_trace_mlp_kernel<<<blocks, TPB>>>(origins, dirs, center, radius,
                                             W1, b1, W2, b2, out, n);
}